// round 11
// baseline (speedup 1.0000x reference)
#include <cuda_runtime.h>
#include <cuda_fp16.h>
#include <math.h>
#include <stdint.h>

// Problem shape (fixed): x = [4, 4096, 64] fp32 -> out [4, 4096, 4096] fp32
#define BN    4096
#define BD    64
#define NB    4
#define TILE  128
#define TPD   (BN / TILE)                  // 32
#define PAIRS (TPD * (TPD + 1) / 2)        // 528
#define NBLK  (NB * PAIRS)                 // 2112 CTAs per pass
#define TPB   256

// SMEM layout (bytes). fp16 tiles use pitch 72 halves (144B) -> conflict-free
// ldmatrix. Mirror stage (MODE 1 only) reuses the tile region.
#define SM_SQA   0                         // 128 fp32 (also reused as reduce pad)
#define SM_SQB   512                       // 128 fp32
#define SM_T     1024                      // 2 tiles x 128 x 144B
#define TILE_PITCH_B 144
#define TILE_BYTES   (128 * TILE_PITCH_B)  // 18432
#define SM_STT   SM_T                      // fp32 [128][pitch 136] = 69632
#define STT_PITCH 136
#define SM_TOTAL0 (1024 + 2 * TILE_BYTES)  // 37888 (pass 0: no stage)
#define SM_TOTAL1 (1024 + 69632)           // 70656 (pass 1: stage > 2 tiles)

// ---- device globals (static scratch; no allocations) ----------------------
__device__ __half  g_xh[(size_t)NB * BN * BD];
__device__ float    g_sq[NB * BN];
__device__ unsigned g_max_bits;
__device__ unsigned g_min_bits;

// ---- helpers ---------------------------------------------------------------
__device__ __forceinline__ void mma16816(float* c, const unsigned* a, const unsigned* b) {
    asm volatile(
        "mma.sync.aligned.m16n8k16.row.col.f32.f16.f16.f32 "
        "{%0,%1,%2,%3}, {%4,%5,%6,%7}, {%8,%9}, {%0,%1,%2,%3};"
        : "+f"(c[0]), "+f"(c[1]), "+f"(c[2]), "+f"(c[3])
        : "r"(a[0]), "r"(a[1]), "r"(a[2]), "r"(a[3]), "r"(b[0]), "r"(b[1]));
}
__device__ __forceinline__ void ldm_x4(unsigned* f, uint32_t addr) {
    asm volatile("ldmatrix.sync.aligned.m8n8.x4.shared.b16 {%0,%1,%2,%3}, [%4];"
        : "=r"(f[0]), "=r"(f[1]), "=r"(f[2]), "=r"(f[3]) : "r"(addr));
}
__device__ __forceinline__ float rsqrt_a(float x) {
    float r;
    asm("rsqrt.approx.f32 %0, %1;" : "=f"(r) : "f"(x));
    return r;
}

// ---- prep: x -> fp16, row sums of squares (fp32), init min/max -------------
__global__ __launch_bounds__(256) void hx_prep(const float* __restrict__ x) {
    if (blockIdx.x == 0 && threadIdx.x == 0) {
        g_max_bits = 0u;
        g_min_bits = 0x7F7FFFFFu;
    }
    int f = blockIdx.x * 256 + threadIdx.x;          // float4 index
    float4 v = ((const float4*)x)[f];

    __half2 p0 = __floats2half2_rn(v.x, v.y);
    __half2 p1 = __floats2half2_rn(v.z, v.w);
    ((uint2*)g_xh)[f] = make_uint2(*(unsigned*)&p0, *(unsigned*)&p1);

    float s = v.x * v.x + v.y * v.y + v.z * v.z + v.w * v.w;
    #pragma unroll
    for (int o = 8; o; o >>= 1) s += __shfl_down_sync(0xffffffffu, s, o, 16);
    if ((threadIdx.x & 15) == 0) g_sq[f >> 4] = s;
}

// ---- main: single-term fp16 HMMA Gram tile. MODE 0: min/max. MODE 1: write.
template <int MODE>
__global__ __launch_bounds__(TPB) void hx_mma(float* __restrict__ out) {
    extern __shared__ char smem[];
    const int tid  = threadIdx.x;
    const int wid  = tid >> 5;
    const int lane = tid & 31;
    const int q    = lane >> 2;    // 0..7
    const int t4   = lane & 3;     // 0..3
    const int wm   = wid >> 2;     // 0..1 : 64-row band
    const int wn   = wid & 3;      // 0..3 : 32-col band

    // Decode block -> (b, ti, tj), ti <= tj
    int bidx = blockIdx.x;
    int b = bidx / PAIRS;
    int p = bidx - b * PAIRS;
    int ti = 0, span = TPD;
    while (p >= span) { p -= span; --span; ++ti; }
    int tj = ti + p;
    const bool diag = (ti == tj);
    const int tibase = ti * TILE, tjbase = tj * TILE;

    float mn = 0.f, inv = 0.f;
    if (MODE == 1) {   // constants from pass 0 (launch-ordered)
        float d2min = __uint_as_float(g_min_bits);
        float d2max = __uint_as_float(g_max_bits);
        mn = (d2min > 0.f) ? d2min * rsqrt_a(d2min) : 0.f;
        inv = 1.0f / (d2max * rsqrt_a(d2max) - mn);
    }

    // Load 2 fp16 tiles (A rows ti*128.., B rows tj*128..), [128][64], pitch 144B.
    #pragma unroll
    for (int it = 0; it < 8; ++it) {
        int idx = it * TPB + tid;            // 0..2047
        int t   = idx >> 10;                 // 0 = A, 1 = B
        int rem = idx & 1023;
        int row = rem >> 3;
        int ch  = rem & 7;
        int row0 = (t ? tj : ti) * TILE;
        uint4 v = *(const uint4*)(g_xh + ((size_t)b * BN + row0 + row) * BD + ch * 8);
        *(uint4*)(smem + SM_T + t * TILE_BYTES + row * TILE_PITCH_B + ch * 16) = v;
    }
    if (tid < 128)       ((float*)(smem + SM_SQA))[tid]       = g_sq[b * BN + tibase + tid];
    else                 ((float*)(smem + SM_SQB))[tid - 128] = g_sq[b * BN + tjbase + tid - 128];
    __syncthreads();

    // ldmatrix lane addressing (A x4 per mt; B x4 covers two nt at once).
    uint32_t sBase = (uint32_t)__cvta_generic_to_shared(smem + SM_T);
    uint32_t aAddr[4], bAddr[2];
    {
        int aRow = lane & 15;
        int aCol = (lane >> 4) << 4;
        #pragma unroll
        for (int mt = 0; mt < 4; ++mt)
            aAddr[mt] = sBase + (uint32_t)((wm * 64 + mt * 16 + aRow) * TILE_PITCH_B + aCol);
        int bRow = lane & 7;
        int bCol = (lane & 8) ? 16 : 0;
        int bSel = (lane >> 4) & 1;
        #pragma unroll
        for (int j = 0; j < 2; ++j) {
            int n0 = wn * 32 + (2 * j + bSel) * 8 + bRow;
            bAddr[j] = sBase + (uint32_t)(TILE_BYTES + n0 * TILE_PITCH_B + bCol);
        }
    }

    float acc[4][4][4];
    #pragma unroll
    for (int i = 0; i < 4; ++i)
        #pragma unroll
        for (int j = 0; j < 4; ++j)
            #pragma unroll
            for (int e = 0; e < 4; ++e) acc[i][j][e] = 0.f;

    // Mainloop: per kc, 6 ldmatrix.x4 + 16 HMMA per warp; 4 kc total.
    #pragma unroll
    for (int kc = 0; kc < 4; ++kc) {
        unsigned A[4][4], B[4][2];
        #pragma unroll
        for (int mt = 0; mt < 4; ++mt) ldm_x4(A[mt], aAddr[mt] + kc * 32);
        {
            unsigned t0[4], t1[4];
            ldm_x4(t0, bAddr[0] + kc * 32);
            ldm_x4(t1, bAddr[1] + kc * 32);
            B[0][0] = t0[0]; B[0][1] = t0[1]; B[1][0] = t0[2]; B[1][1] = t0[3];
            B[2][0] = t1[0]; B[2][1] = t1[1]; B[3][0] = t1[2]; B[3][1] = t1[3];
        }
        #pragma unroll
        for (int mt = 0; mt < 4; ++mt)
            #pragma unroll
            for (int nt = 0; nt < 4; ++nt) mma16816(acc[mt][nt], A[mt], B[nt]);
    }

    // Per-thread row/col sums of squares.
    const float* sqa = (const float*)(smem + SM_SQA);
    const float* sqb = (const float*)(smem + SM_SQB);
    float sr0[4], sr1[4], sc0[4], sc1[4];
    #pragma unroll
    for (int mt = 0; mt < 4; ++mt) {
        sr0[mt] = sqa[wm * 64 + mt * 16 + q];
        sr1[mt] = sqa[wm * 64 + mt * 16 + q + 8];
    }
    #pragma unroll
    for (int nt = 0; nt < 4; ++nt) {
        sc0[nt] = sqb[wn * 32 + nt * 8 + t4 * 2];
        sc1[nt] = sqb[wn * 32 + nt * 8 + t4 * 2 + 1];
    }

    if (MODE == 0) {
        float tmax = 0.f, tmin = 3.402823466e38f;
        #pragma unroll
        for (int mt = 0; mt < 4; ++mt)
            #pragma unroll
            for (int nt = 0; nt < 4; ++nt) {
                float d00 = fmaxf(fmaf(-2.f, acc[mt][nt][0], sr0[mt] + sc0[nt]), 0.f);
                float d01 = fmaxf(fmaf(-2.f, acc[mt][nt][1], sr0[mt] + sc1[nt]), 0.f);
                float d10 = fmaxf(fmaf(-2.f, acc[mt][nt][2], sr1[mt] + sc0[nt]), 0.f);
                float d11 = fmaxf(fmaf(-2.f, acc[mt][nt][3], sr1[mt] + sc1[nt]), 0.f);
                tmax = fmaxf(tmax, fmaxf(fmaxf(d00, d01), fmaxf(d10, d11)));
                tmin = fminf(tmin, fminf(fminf(d00, d01), fminf(d10, d11)));
            }
        #pragma unroll
        for (int o = 16; o; o >>= 1) {
            tmax = fmaxf(tmax, __shfl_xor_sync(0xffffffffu, tmax, o));
            tmin = fminf(tmin, __shfl_xor_sync(0xffffffffu, tmin, o));
        }
        // Block-level reduce -> ONE atomic pair per CTA (was 8; atomics to a
        // single L2 address serialize and dominated pass-0 time).
        __syncthreads();                      // sqa/sqb reads done; reuse pad
        float* redmx = (float*)(smem + SM_SQA);
        float* redmn = redmx + 8;
        if (lane == 0) { redmx[wid] = tmax; redmn[wid] = tmin; }
        __syncthreads();
        if (wid == 0 && lane < 8) {
            float m = redmx[lane], n = redmn[lane];
            #pragma unroll
            for (int o = 4; o; o >>= 1) {
                m = fmaxf(m, __shfl_down_sync(0xffu, m, o, 8));
                n = fminf(n, __shfl_down_sync(0xffu, n, o, 8));
            }
            if (lane == 0) {
                atomicMax(&g_max_bits, __float_as_uint(m));
                atomicMin(&g_min_bits, __float_as_uint(n));
            }
        }
        return;
    }

    // MODE 1: normalize in registers, store main tile, stage + store mirror.
    float* ob = out + (size_t)b * BN * BN;
    #pragma unroll
    for (int mt = 0; mt < 4; ++mt) {
        int r0 = wm * 64 + mt * 16 + q, r1 = r0 + 8;
        #pragma unroll
        for (int nt = 0; nt < 4; ++nt) {
            int c0 = wn * 32 + nt * 8 + t4 * 2;
            float d2, d;
            d2 = fmaf(-2.f, acc[mt][nt][0], sr0[mt] + sc0[nt]);
            d  = (d2 > 0.f) ? d2 * rsqrt_a(d2) : 0.f;
            acc[mt][nt][0] = (diag && r0 == c0)     ? 1.0f : (d - mn) * inv;
            d2 = fmaf(-2.f, acc[mt][nt][1], sr0[mt] + sc1[nt]);
            d  = (d2 > 0.f) ? d2 * rsqrt_a(d2) : 0.f;
            acc[mt][nt][1] = (diag && r0 == c0 + 1) ? 1.0f : (d - mn) * inv;
            d2 = fmaf(-2.f, acc[mt][nt][2], sr1[mt] + sc0[nt]);
            d  = (d2 > 0.f) ? d2 * rsqrt_a(d2) : 0.f;
            acc[mt][nt][2] = (diag && r1 == c0)     ? 1.0f : (d - mn) * inv;
            d2 = fmaf(-2.f, acc[mt][nt][3], sr1[mt] + sc1[nt]);
            d  = (d2 > 0.f) ? d2 * rsqrt_a(d2) : 0.f;
            acc[mt][nt][3] = (diag && r1 == c0 + 1) ? 1.0f : (d - mn) * inv;
            *(float2*)(ob + (size_t)(tibase + r0) * BN + tjbase + c0) =
                make_float2(acc[mt][nt][0], acc[mt][nt][1]);
            *(float2*)(ob + (size_t)(tibase + r1) * BN + tjbase + c0) =
                make_float2(acc[mt][nt][2], acc[mt][nt][3]);
        }
    }

    if (!diag) {
        __syncthreads();                     // tiles dead -> reuse as stage
        float* st = (float*)(smem + SM_STT); // [col][row], pitch 136
        #pragma unroll
        for (int mt = 0; mt < 4; ++mt) {
            int r0 = wm * 64 + mt * 16 + q, r1 = r0 + 8;
            #pragma unroll
            for (int nt = 0; nt < 4; ++nt) {
                int c0 = wn * 32 + nt * 8 + t4 * 2;
                st[(c0)     * STT_PITCH + r0] = acc[mt][nt][0];
                st[(c0 + 1) * STT_PITCH + r0] = acc[mt][nt][1];
                st[(c0)     * STT_PITCH + r1] = acc[mt][nt][2];
                st[(c0 + 1) * STT_PITCH + r1] = acc[mt][nt][3];
            }
        }
        __syncthreads();
        #pragma unroll
        for (int i = 0; i < 16; ++i) {
            int idx = i * TPB + tid;
            int mc = idx >> 5, g = idx & 31;
            float4 w = *(const float4*)(st + mc * STT_PITCH + g * 4);
            *(float4*)(ob + (size_t)(tjbase + mc) * BN + tibase + g * 4) = w;
        }
    }
}

extern "C" void kernel_launch(void* const* d_in, const int* in_sizes, int n_in,
                              void* d_out, int out_size) {
    const float* x = (const float*)d_in[0];
    float* out = (float*)d_out;

    cudaFuncSetAttribute(hx_mma<0>, cudaFuncAttributeMaxDynamicSharedMemorySize, SM_TOTAL0);
    cudaFuncSetAttribute(hx_mma<1>, cudaFuncAttributeMaxDynamicSharedMemorySize, SM_TOTAL1);

    hx_prep<<<(NB * BN * BD / 4) / 256, 256>>>(x);     // fp16 convert + sq + init
    hx_mma<0><<<NBLK, TPB, SM_TOTAL0>>>(out);          // global min/max of d2 (occ 6)
    hx_mma<1><<<NBLK, TPB, SM_TOTAL1>>>(out);          // recompute + normalize + write
}

// round 12
// speedup vs baseline: 1.0618x; 1.0618x over previous
#include <cuda_runtime.h>
#include <cuda_fp16.h>
#include <math.h>
#include <stdint.h>

// Problem shape (fixed): x = [4, 4096, 64] fp32 -> out [4, 4096, 4096] fp32
#define BN    4096
#define BD    64
#define NB    4
#define TILE  128
#define TPD   (BN / TILE)                  // 32
#define PAIRS (TPD * (TPD + 1) / 2)        // 528
#define NBLK  (NB * PAIRS)                 // 2112 CTAs per pass
#define TPB   256

// SMEM layout (bytes). fp16 tiles use pitch 72 halves (144B) -> conflict-free
// ldmatrix. Mirror stage (MODE 1 only) reuses the tile region.
#define SM_SQA   0                         // 128 fp32 (also reduce pad)
#define SM_SQB   512                       // 128 fp32
#define SM_T     1024                      // 2 tiles x 128 x 144B
#define TILE_PITCH_B 144
#define TILE_BYTES   (128 * TILE_PITCH_B)  // 18432
#define SM_STT   SM_T                      // fp32 [128][pitch 136] = 69632
#define STT_PITCH 136
#define SM_TOTAL0 (1024 + 2 * TILE_BYTES)  // 37888 (pass 0: no stage)
#define SM_TOTAL1 (1024 + 69632)           // 70656 (pass 1)

// ---- device globals (static scratch; no allocations) ----------------------
__device__ __half  g_xh[(size_t)NB * BN * BD];
__device__ float    g_sq[NB * BN];
__device__ unsigned g_max_bits;
__device__ unsigned g_min_bits;

// ---- helpers ---------------------------------------------------------------
__device__ __forceinline__ void mma16816(float* c, const unsigned* a, const unsigned* b) {
    asm volatile(
        "mma.sync.aligned.m16n8k16.row.col.f32.f16.f16.f32 "
        "{%0,%1,%2,%3}, {%4,%5,%6,%7}, {%8,%9}, {%0,%1,%2,%3};"
        : "+f"(c[0]), "+f"(c[1]), "+f"(c[2]), "+f"(c[3])
        : "r"(a[0]), "r"(a[1]), "r"(a[2]), "r"(a[3]), "r"(b[0]), "r"(b[1]));
}
__device__ __forceinline__ void ldm_x4(unsigned* f, uint32_t addr) {
    asm volatile("ldmatrix.sync.aligned.m8n8.x4.shared.b16 {%0,%1,%2,%3}, [%4];"
        : "=r"(f[0]), "=r"(f[1]), "=r"(f[2]), "=r"(f[3]) : "r"(addr));
}
__device__ __forceinline__ float rsqrt_a(float x) {
    float r;
    asm("rsqrt.approx.f32 %0, %1;" : "=f"(r) : "f"(x));
    return r;
}
// Streaming (evict-first) stores: output is write-once, keep it out of L2.
__device__ __forceinline__ void stg_cs64(float* p, float a, float b) {
    asm volatile("st.global.cs.v2.f32 [%0], {%1,%2};" :: "l"(p), "f"(a), "f"(b) : "memory");
}
__device__ __forceinline__ void stg_cs128(float* p, float4 v) {
    asm volatile("st.global.cs.v4.f32 [%0], {%1,%2,%3,%4};"
                 :: "l"(p), "f"(v.x), "f"(v.y), "f"(v.z), "f"(v.w) : "memory");
}
// cp.async 16B gmem->smem (base ISA sm_80+)
__device__ __forceinline__ void cp16(uint32_t dst, const void* src) {
    asm volatile("cp.async.ca.shared.global [%0], [%1], 16;" :: "r"(dst), "l"(src) : "memory");
}

// ---- prep: x -> fp16, row sums of squares (fp32), init min/max -------------
__global__ __launch_bounds__(256) void hx_prep(const float* __restrict__ x) {
    if (blockIdx.x == 0 && threadIdx.x == 0) {
        g_max_bits = 0u;
        g_min_bits = 0x7F7FFFFFu;
    }
    int f = blockIdx.x * 256 + threadIdx.x;          // float4 index
    float4 v = ((const float4*)x)[f];

    __half2 p0 = __floats2half2_rn(v.x, v.y);
    __half2 p1 = __floats2half2_rn(v.z, v.w);
    ((uint2*)g_xh)[f] = make_uint2(*(unsigned*)&p0, *(unsigned*)&p1);

    float s = v.x * v.x + v.y * v.y + v.z * v.z + v.w * v.w;
    #pragma unroll
    for (int o = 8; o; o >>= 1) s += __shfl_down_sync(0xffffffffu, s, o, 16);
    if ((threadIdx.x & 15) == 0) g_sq[f >> 4] = s;
}

// ---- main: single-term fp16 HMMA Gram tile. MODE 0: min/max. MODE 1: write.
template <int MODE>
__global__ __launch_bounds__(TPB, 2) void hx_mma(float* __restrict__ out) {
    extern __shared__ char smem[];
    const int tid  = threadIdx.x;
    const int wid  = tid >> 5;
    const int lane = tid & 31;
    const int q    = lane >> 2;    // 0..7
    const int t4   = lane & 3;     // 0..3
    const int wm   = wid >> 2;     // 0..1 : 64-row band
    const int wn   = wid & 3;      // 0..3 : 32-col band

    // Decode block -> (b, ti, tj), ti <= tj
    int bidx = blockIdx.x;
    int b = bidx / PAIRS;
    int p = bidx - b * PAIRS;
    int ti = 0, span = TPD;
    while (p >= span) { p -= span; --span; ++ti; }
    int tj = ti + p;
    const bool diag = (ti == tj);
    const int tibase = ti * TILE, tjbase = tj * TILE;

    float mn = 0.f, inv = 0.f;
    if (MODE == 1) {   // constants from pass 0 (launch-ordered)
        float d2min = __uint_as_float(g_min_bits);
        float d2max = __uint_as_float(g_max_bits);
        mn = (d2min > 0.f) ? d2min * rsqrt_a(d2min) : 0.f;
        inv = 1.0f / (d2max * rsqrt_a(d2max) - mn);
    }

    uint32_t smemBase = (uint32_t)__cvta_generic_to_shared(smem);

    // Async-load 2 fp16 tiles (A rows ti*128.., B rows tj*128..), pitch 144B.
    #pragma unroll
    for (int it = 0; it < 8; ++it) {
        int idx = it * TPB + tid;            // 0..2047
        int t   = idx >> 10;                 // 0 = A, 1 = B
        int rem = idx & 1023;
        int row = rem >> 3;
        int ch  = rem & 7;
        int row0 = (t ? tj : ti) * TILE;
        cp16(smemBase + SM_T + t * TILE_BYTES + row * TILE_PITCH_B + ch * 16,
             g_xh + ((size_t)b * BN + row0 + row) * BD + ch * 8);
    }
    asm volatile("cp.async.commit_group;" ::: "memory");
    if (tid < 128)       ((float*)(smem + SM_SQA))[tid]       = g_sq[b * BN + tibase + tid];
    else                 ((float*)(smem + SM_SQB))[tid - 128] = g_sq[b * BN + tjbase + tid - 128];
    asm volatile("cp.async.wait_group 0;" ::: "memory");
    __syncthreads();

    // ldmatrix lane addressing (A x4 per mt; B x4 covers two nt at once).
    uint32_t sBase = smemBase + SM_T;
    uint32_t aAddr[4], bAddr[2];
    {
        int aRow = lane & 15;
        int aCol = (lane >> 4) << 4;
        #pragma unroll
        for (int mt = 0; mt < 4; ++mt)
            aAddr[mt] = sBase + (uint32_t)((wm * 64 + mt * 16 + aRow) * TILE_PITCH_B + aCol);
        int bRow = lane & 7;
        int bCol = (lane & 8) ? 16 : 0;
        int bSel = (lane >> 4) & 1;
        #pragma unroll
        for (int j = 0; j < 2; ++j) {
            int n0 = wn * 32 + (2 * j + bSel) * 8 + bRow;
            bAddr[j] = sBase + (uint32_t)(TILE_BYTES + n0 * TILE_PITCH_B + bCol);
        }
    }

    float acc[4][4][4];
    #pragma unroll
    for (int i = 0; i < 4; ++i)
        #pragma unroll
        for (int j = 0; j < 4; ++j)
            #pragma unroll
            for (int e = 0; e < 4; ++e) acc[i][j][e] = 0.f;

    // Mainloop: per kc, 6 ldmatrix.x4 + 16 HMMA per warp; 4 kc total.
    #pragma unroll
    for (int kc = 0; kc < 4; ++kc) {
        unsigned A[4][4], B[4][2];
        #pragma unroll
        for (int mt = 0; mt < 4; ++mt) ldm_x4(A[mt], aAddr[mt] + kc * 32);
        {
            unsigned t0[4], t1[4];
            ldm_x4(t0, bAddr[0] + kc * 32);
            ldm_x4(t1, bAddr[1] + kc * 32);
            B[0][0] = t0[0]; B[0][1] = t0[1]; B[1][0] = t0[2]; B[1][1] = t0[3];
            B[2][0] = t1[0]; B[2][1] = t1[1]; B[3][0] = t1[2]; B[3][1] = t1[3];
        }
        #pragma unroll
        for (int mt = 0; mt < 4; ++mt)
            #pragma unroll
            for (int nt = 0; nt < 4; ++nt) mma16816(acc[mt][nt], A[mt], B[nt]);
    }

    // Per-thread row/col sums of squares.
    const float* sqa = (const float*)(smem + SM_SQA);
    const float* sqb = (const float*)(smem + SM_SQB);
    float sr0[4], sr1[4], sc0[4], sc1[4];
    #pragma unroll
    for (int mt = 0; mt < 4; ++mt) {
        sr0[mt] = sqa[wm * 64 + mt * 16 + q];
        sr1[mt] = sqa[wm * 64 + mt * 16 + q + 8];
    }
    #pragma unroll
    for (int nt = 0; nt < 4; ++nt) {
        sc0[nt] = sqb[wn * 32 + nt * 8 + t4 * 2];
        sc1[nt] = sqb[wn * 32 + nt * 8 + t4 * 2 + 1];
    }

    if (MODE == 0) {
        float tmax = 0.f, tmin = 3.402823466e38f;
        #pragma unroll
        for (int mt = 0; mt < 4; ++mt)
            #pragma unroll
            for (int nt = 0; nt < 4; ++nt) {
                float d00 = fmaxf(fmaf(-2.f, acc[mt][nt][0], sr0[mt] + sc0[nt]), 0.f);
                float d01 = fmaxf(fmaf(-2.f, acc[mt][nt][1], sr0[mt] + sc1[nt]), 0.f);
                float d10 = fmaxf(fmaf(-2.f, acc[mt][nt][2], sr1[mt] + sc0[nt]), 0.f);
                float d11 = fmaxf(fmaf(-2.f, acc[mt][nt][3], sr1[mt] + sc1[nt]), 0.f);
                tmax = fmaxf(tmax, fmaxf(fmaxf(d00, d01), fmaxf(d10, d11)));
                tmin = fminf(tmin, fminf(fminf(d00, d01), fminf(d10, d11)));
            }
        #pragma unroll
        for (int o = 16; o; o >>= 1) {
            tmax = fmaxf(tmax, __shfl_xor_sync(0xffffffffu, tmax, o));
            tmin = fminf(tmin, __shfl_xor_sync(0xffffffffu, tmin, o));
        }
        __syncthreads();
        float* redmx = (float*)(smem + SM_SQA);
        float* redmn = redmx + 8;
        if (lane == 0) { redmx[wid] = tmax; redmn[wid] = tmin; }
        __syncthreads();
        if (wid == 0 && lane < 8) {
            float m = redmx[lane], n = redmn[lane];
            #pragma unroll
            for (int o = 4; o; o >>= 1) {
                m = fmaxf(m, __shfl_down_sync(0xffu, m, o, 8));
                n = fminf(n, __shfl_down_sync(0xffu, n, o, 8));
            }
            if (lane == 0) {
                atomicMax(&g_max_bits, __float_as_uint(m));
                atomicMin(&g_min_bits, __float_as_uint(n));
            }
        }
        return;
    }

    // MODE 1: normalize in registers, stream main tile, stage + stream mirror.
    float* ob = out + (size_t)b * BN * BN;
    #pragma unroll
    for (int mt = 0; mt < 4; ++mt) {
        int r0 = wm * 64 + mt * 16 + q, r1 = r0 + 8;
        #pragma unroll
        for (int nt = 0; nt < 4; ++nt) {
            int c0 = wn * 32 + nt * 8 + t4 * 2;
            float d2, d;
            d2 = fmaf(-2.f, acc[mt][nt][0], sr0[mt] + sc0[nt]);
            d  = (d2 > 0.f) ? d2 * rsqrt_a(d2) : 0.f;
            acc[mt][nt][0] = (diag && r0 == c0)     ? 1.0f : (d - mn) * inv;
            d2 = fmaf(-2.f, acc[mt][nt][1], sr0[mt] + sc1[nt]);
            d  = (d2 > 0.f) ? d2 * rsqrt_a(d2) : 0.f;
            acc[mt][nt][1] = (diag && r0 == c0 + 1) ? 1.0f : (d - mn) * inv;
            d2 = fmaf(-2.f, acc[mt][nt][2], sr1[mt] + sc0[nt]);
            d  = (d2 > 0.f) ? d2 * rsqrt_a(d2) : 0.f;
            acc[mt][nt][2] = (diag && r1 == c0)     ? 1.0f : (d - mn) * inv;
            d2 = fmaf(-2.f, acc[mt][nt][3], sr1[mt] + sc1[nt]);
            d  = (d2 > 0.f) ? d2 * rsqrt_a(d2) : 0.f;
            acc[mt][nt][3] = (diag && r1 == c0 + 1) ? 1.0f : (d - mn) * inv;
            stg_cs64(ob + (size_t)(tibase + r0) * BN + tjbase + c0,
                     acc[mt][nt][0], acc[mt][nt][1]);
            stg_cs64(ob + (size_t)(tibase + r1) * BN + tjbase + c0,
                     acc[mt][nt][2], acc[mt][nt][3]);
        }
    }

    if (!diag) {
        __syncthreads();                     // tiles dead -> reuse as stage
        float* st = (float*)(smem + SM_STT); // [col][row], pitch 136
        #pragma unroll
        for (int mt = 0; mt < 4; ++mt) {
            int r0 = wm * 64 + mt * 16 + q, r1 = r0 + 8;
            #pragma unroll
            for (int nt = 0; nt < 4; ++nt) {
                int c0 = wn * 32 + nt * 8 + t4 * 2;
                st[(c0)     * STT_PITCH + r0] = acc[mt][nt][0];
                st[(c0 + 1) * STT_PITCH + r0] = acc[mt][nt][1];
                st[(c0)     * STT_PITCH + r1] = acc[mt][nt][2];
                st[(c0 + 1) * STT_PITCH + r1] = acc[mt][nt][3];
            }
        }
        __syncthreads();
        #pragma unroll
        for (int i = 0; i < 16; ++i) {
            int idx = i * TPB + tid;
            int mc = idx >> 5, g = idx & 31;
            float4 w = *(const float4*)(st + mc * STT_PITCH + g * 4);
            stg_cs128(ob + (size_t)(tjbase + mc) * BN + tibase + g * 4, w);
        }
    }
}

extern "C" void kernel_launch(void* const* d_in, const int* in_sizes, int n_in,
                              void* d_out, int out_size) {
    const float* x = (const float*)d_in[0];
    float* out = (float*)d_out;

    cudaFuncSetAttribute(hx_mma<0>, cudaFuncAttributeMaxDynamicSharedMemorySize, SM_TOTAL0);
    cudaFuncSetAttribute(hx_mma<1>, cudaFuncAttributeMaxDynamicSharedMemorySize, SM_TOTAL1);

    hx_prep<<<(NB * BN * BD / 4) / 256, 256>>>(x);     // fp16 convert + sq + init
    hx_mma<0><<<NBLK, TPB, SM_TOTAL0>>>(out);          // global min/max of d2
    hx_mma<1><<<NBLK, TPB, SM_TOTAL1>>>(out);          // recompute + normalize + write
}

// round 13
// speedup vs baseline: 1.1069x; 1.0424x over previous
#include <cuda_runtime.h>
#include <cuda_fp16.h>
#include <math.h>
#include <stdint.h>

// Problem shape (fixed): x = [4, 4096, 64] fp32 -> out [4, 4096, 4096] fp32
#define BN    4096
#define BD    64
#define NB    4
#define TILE  128
#define TPD   (BN / TILE)                  // 32
#define NOFF  (TPD * (TPD - 1) / 2)        // 496 off-diag pairs
#define PAIRS (NOFF + TPD)                 // 528
#define NBLK  (NB * PAIRS)                 // 2112 CTAs per pass
#define TPB   256

// SMEM layout (bytes). fp16 tiles use pitch 72 halves (144B) -> conflict-free
// ldmatrix. Mirror stage (MODE 1) reuses tile region in 64-col chunks.
#define SM_SQA   0                         // 128 fp32 (also reduce pad)
#define SM_SQB   512                       // 128 fp32
#define SM_T     1024                      // 2 tiles x 128 x 144B
#define TILE_PITCH_B 144
#define TILE_BYTES   (128 * TILE_PITCH_B)  // 18432
#define SM_STT   SM_T                      // fp32 [64][pitch 136] = 34816 (fits in tiles)
#define STT_PITCH 136
#define SM_TOTAL (1024 + 2 * TILE_BYTES)   // 37888 (both passes)

// ---- device globals (static scratch; no allocations) ----------------------
__device__ __half  g_xh[(size_t)NB * BN * BD];
__device__ float    g_sq[NB * BN];
__device__ unsigned g_max_bits;
__device__ unsigned g_min_bits;

// ---- helpers ---------------------------------------------------------------
__device__ __forceinline__ void mma16816(float* c, const unsigned* a, const unsigned* b) {
    asm volatile(
        "mma.sync.aligned.m16n8k16.row.col.f32.f16.f16.f32 "
        "{%0,%1,%2,%3}, {%4,%5,%6,%7}, {%8,%9}, {%0,%1,%2,%3};"
        : "+f"(c[0]), "+f"(c[1]), "+f"(c[2]), "+f"(c[3])
        : "r"(a[0]), "r"(a[1]), "r"(a[2]), "r"(a[3]), "r"(b[0]), "r"(b[1]));
}
__device__ __forceinline__ void ldm_x4(unsigned* f, uint32_t addr) {
    asm volatile("ldmatrix.sync.aligned.m8n8.x4.shared.b16 {%0,%1,%2,%3}, [%4];"
        : "=r"(f[0]), "=r"(f[1]), "=r"(f[2]), "=r"(f[3]) : "r"(addr));
}
__device__ __forceinline__ float rsqrt_a(float x) {
    float r;
    asm("rsqrt.approx.f32 %0, %1;" : "=f"(r) : "f"(x));
    return r;
}
__device__ __forceinline__ void stg_cs64(float* p, float a, float b) {
    asm volatile("st.global.cs.v2.f32 [%0], {%1,%2};" :: "l"(p), "f"(a), "f"(b) : "memory");
}
__device__ __forceinline__ void stg_cs128(float* p, float4 v) {
    asm volatile("st.global.cs.v4.f32 [%0], {%1,%2,%3,%4};"
                 :: "l"(p), "f"(v.x), "f"(v.y), "f"(v.z), "f"(v.w) : "memory");
}
__device__ __forceinline__ void cp16(uint32_t dst, const void* src) {
    asm volatile("cp.async.ca.shared.global [%0], [%1], 16;" :: "r"(dst), "l"(src) : "memory");
}

// ---- prep: x -> fp16, row sums of squares (fp32), init min/max -------------
__global__ __launch_bounds__(256) void hx_prep(const float* __restrict__ x) {
    if (blockIdx.x == 0 && threadIdx.x == 0) {
        g_max_bits = 0u;
        g_min_bits = 0x7F7FFFFFu;
    }
    int f = blockIdx.x * 256 + threadIdx.x;          // float4 index
    float4 v = ((const float4*)x)[f];

    __half2 p0 = __floats2half2_rn(v.x, v.y);
    __half2 p1 = __floats2half2_rn(v.z, v.w);
    ((uint2*)g_xh)[f] = make_uint2(*(unsigned*)&p0, *(unsigned*)&p1);

    float s = v.x * v.x + v.y * v.y + v.z * v.z + v.w * v.w;
    #pragma unroll
    for (int o = 8; o; o >>= 1) s += __shfl_down_sync(0xffffffffu, s, o, 16);
    if ((threadIdx.x & 15) == 0) g_sq[f >> 4] = s;
}

// ---- main: single-term fp16 HMMA Gram tile. MODE 0: min/max. MODE 1: write.
template <int MODE>
__global__ __launch_bounds__(TPB, MODE == 0 ? 3 : 2) void hx_mma(float* __restrict__ out) {
    extern __shared__ char smem[];
    const int tid  = threadIdx.x;
    const int wid  = tid >> 5;
    const int lane = tid & 31;
    const int q    = lane >> 2;    // 0..7
    const int t4   = lane & 3;     // 0..3
    const int wm   = wid >> 2;     // 0..1 : 64-row band
    const int wn   = wid & 3;      // 0..3 : 32-col band

    // Decode block -> (b, ti, tj). Off-diag pairs first (ti < tj), diagonal
    // tiles last so the final partial wave holds the cheapest CTAs.
    int bidx = blockIdx.x;
    int b = bidx / PAIRS;
    int p = bidx - b * PAIRS;
    int ti, tj;
    if (p < NOFF) {
        ti = 0;
        int span = TPD - 1;
        while (p >= span) { p -= span; --span; ++ti; }
        tj = ti + 1 + p;
    } else {
        ti = tj = p - NOFF;
    }
    const bool diag = (ti == tj);
    const int tibase = ti * TILE, tjbase = tj * TILE;

    float mn = 0.f, inv = 0.f;
    if (MODE == 1) {   // constants from pass 0 (launch-ordered)
        float d2min = __uint_as_float(g_min_bits);
        float d2max = __uint_as_float(g_max_bits);
        mn = (d2min > 0.f) ? d2min * rsqrt_a(d2min) : 0.f;
        inv = 1.0f / (d2max * rsqrt_a(d2max) - mn);
    }

    uint32_t smemBase = (uint32_t)__cvta_generic_to_shared(smem);

    // Async-load 2 fp16 tiles (A rows ti*128.., B rows tj*128..), pitch 144B.
    #pragma unroll
    for (int it = 0; it < 8; ++it) {
        int idx = it * TPB + tid;            // 0..2047
        int t   = idx >> 10;                 // 0 = A, 1 = B
        int rem = idx & 1023;
        int row = rem >> 3;
        int ch  = rem & 7;
        int row0 = (t ? tj : ti) * TILE;
        cp16(smemBase + SM_T + t * TILE_BYTES + row * TILE_PITCH_B + ch * 16,
             g_xh + ((size_t)b * BN + row0 + row) * BD + ch * 8);
    }
    asm volatile("cp.async.commit_group;" ::: "memory");
    if (tid < 128)       ((float*)(smem + SM_SQA))[tid]       = g_sq[b * BN + tibase + tid];
    else                 ((float*)(smem + SM_SQB))[tid - 128] = g_sq[b * BN + tjbase + tid - 128];
    asm volatile("cp.async.wait_group 0;" ::: "memory");
    __syncthreads();

    // ldmatrix lane addressing (A x4 per mt; B x4 covers two nt at once).
    uint32_t sBase = smemBase + SM_T;
    uint32_t aAddr[4], bAddr[2];
    {
        int aRow = lane & 15;
        int aCol = (lane >> 4) << 4;
        #pragma unroll
        for (int mt = 0; mt < 4; ++mt)
            aAddr[mt] = sBase + (uint32_t)((wm * 64 + mt * 16 + aRow) * TILE_PITCH_B + aCol);
        int bRow = lane & 7;
        int bCol = (lane & 8) ? 16 : 0;
        int bSel = (lane >> 4) & 1;
        #pragma unroll
        for (int j = 0; j < 2; ++j) {
            int n0 = wn * 32 + (2 * j + bSel) * 8 + bRow;
            bAddr[j] = sBase + (uint32_t)(TILE_BYTES + n0 * TILE_PITCH_B + bCol);
        }
    }

    float acc[4][4][4];
    #pragma unroll
    for (int i = 0; i < 4; ++i)
        #pragma unroll
        for (int j = 0; j < 4; ++j)
            #pragma unroll
            for (int e = 0; e < 4; ++e) acc[i][j][e] = 0.f;

    // Mainloop: per kc, 6 ldmatrix.x4 + 16 HMMA per warp; 4 kc total.
    #pragma unroll
    for (int kc = 0; kc < 4; ++kc) {
        unsigned A[4][4], B[4][2];
        #pragma unroll
        for (int mt = 0; mt < 4; ++mt) ldm_x4(A[mt], aAddr[mt] + kc * 32);
        {
            unsigned t0[4], t1[4];
            ldm_x4(t0, bAddr[0] + kc * 32);
            ldm_x4(t1, bAddr[1] + kc * 32);
            B[0][0] = t0[0]; B[0][1] = t0[1]; B[1][0] = t0[2]; B[1][1] = t0[3];
            B[2][0] = t1[0]; B[2][1] = t1[1]; B[3][0] = t1[2]; B[3][1] = t1[3];
        }
        #pragma unroll
        for (int mt = 0; mt < 4; ++mt)
            #pragma unroll
            for (int nt = 0; nt < 4; ++nt) mma16816(acc[mt][nt], A[mt], B[nt]);
    }

    // Per-thread row/col sums of squares.
    const float* sqa = (const float*)(smem + SM_SQA);
    const float* sqb = (const float*)(smem + SM_SQB);
    float sr0[4], sr1[4], sc0[4], sc1[4];
    #pragma unroll
    for (int mt = 0; mt < 4; ++mt) {
        sr0[mt] = sqa[wm * 64 + mt * 16 + q];
        sr1[mt] = sqa[wm * 64 + mt * 16 + q + 8];
    }
    #pragma unroll
    for (int nt = 0; nt < 4; ++nt) {
        sc0[nt] = sqb[wn * 32 + nt * 8 + t4 * 2];
        sc1[nt] = sqb[wn * 32 + nt * 8 + t4 * 2 + 1];
    }

    if (MODE == 0) {
        float tmax = 0.f, tmin = 3.402823466e38f;
        #pragma unroll
        for (int mt = 0; mt < 4; ++mt)
            #pragma unroll
            for (int nt = 0; nt < 4; ++nt) {
                float d00 = fmaxf(fmaf(-2.f, acc[mt][nt][0], sr0[mt] + sc0[nt]), 0.f);
                float d01 = fmaxf(fmaf(-2.f, acc[mt][nt][1], sr0[mt] + sc1[nt]), 0.f);
                float d10 = fmaxf(fmaf(-2.f, acc[mt][nt][2], sr1[mt] + sc0[nt]), 0.f);
                float d11 = fmaxf(fmaf(-2.f, acc[mt][nt][3], sr1[mt] + sc1[nt]), 0.f);
                tmax = fmaxf(tmax, fmaxf(fmaxf(d00, d01), fmaxf(d10, d11)));
                tmin = fminf(tmin, fminf(fminf(d00, d01), fminf(d10, d11)));
            }
        #pragma unroll
        for (int o = 16; o; o >>= 1) {
            tmax = fmaxf(tmax, __shfl_xor_sync(0xffffffffu, tmax, o));
            tmin = fminf(tmin, __shfl_xor_sync(0xffffffffu, tmin, o));
        }
        __syncthreads();
        float* redmx = (float*)(smem + SM_SQA);
        float* redmn = redmx + 8;
        if (lane == 0) { redmx[wid] = tmax; redmn[wid] = tmin; }
        __syncthreads();
        if (wid == 0 && lane < 8) {
            float m = redmx[lane], n = redmn[lane];
            #pragma unroll
            for (int o = 4; o; o >>= 1) {
                m = fmaxf(m, __shfl_down_sync(0xffu, m, o, 8));
                n = fminf(n, __shfl_down_sync(0xffu, n, o, 8));
            }
            if (lane == 0) {
                atomicMax(&g_max_bits, __float_as_uint(m));
                atomicMin(&g_min_bits, __float_as_uint(n));
            }
        }
        return;
    }

    // MODE 1: normalize in registers, stream main tile, then mirror in two
    // 64-column chunks (keeps SMEM at 2-tile size; stores drain earlier).
    float* ob = out + (size_t)b * BN * BN;
    #pragma unroll
    for (int mt = 0; mt < 4; ++mt) {
        int r0 = wm * 64 + mt * 16 + q, r1 = r0 + 8;
        #pragma unroll
        for (int nt = 0; nt < 4; ++nt) {
            int c0 = wn * 32 + nt * 8 + t4 * 2;
            float d2, d;
            d2 = fmaf(-2.f, acc[mt][nt][0], sr0[mt] + sc0[nt]);
            d  = (d2 > 0.f) ? d2 * rsqrt_a(d2) : 0.f;
            acc[mt][nt][0] = (diag && r0 == c0)     ? 1.0f : (d - mn) * inv;
            d2 = fmaf(-2.f, acc[mt][nt][1], sr0[mt] + sc1[nt]);
            d  = (d2 > 0.f) ? d2 * rsqrt_a(d2) : 0.f;
            acc[mt][nt][1] = (diag && r0 == c0 + 1) ? 1.0f : (d - mn) * inv;
            d2 = fmaf(-2.f, acc[mt][nt][2], sr1[mt] + sc0[nt]);
            d  = (d2 > 0.f) ? d2 * rsqrt_a(d2) : 0.f;
            acc[mt][nt][2] = (diag && r1 == c0)     ? 1.0f : (d - mn) * inv;
            d2 = fmaf(-2.f, acc[mt][nt][3], sr1[mt] + sc1[nt]);
            d  = (d2 > 0.f) ? d2 * rsqrt_a(d2) : 0.f;
            acc[mt][nt][3] = (diag && r1 == c0 + 1) ? 1.0f : (d - mn) * inv;
            stg_cs64(ob + (size_t)(tibase + r0) * BN + tjbase + c0,
                     acc[mt][nt][0], acc[mt][nt][1]);
            stg_cs64(ob + (size_t)(tibase + r1) * BN + tjbase + c0,
                     acc[mt][nt][2], acc[mt][nt][3]);
        }
    }

    if (!diag) {
        float* st = (float*)(smem + SM_STT);   // [64][pitch 136]
        #pragma unroll
        for (int half = 0; half < 2; ++half) {
            __syncthreads();                   // tiles/prev chunk dead
            if ((wn >> 1) == half) {           // warps owning these 64 cols
                #pragma unroll
                for (int mt = 0; mt < 4; ++mt) {
                    int r0 = wm * 64 + mt * 16 + q, r1 = r0 + 8;
                    #pragma unroll
                    for (int nt = 0; nt < 4; ++nt) {
                        int c0 = wn * 32 + nt * 8 + t4 * 2 - half * 64;
                        st[(c0)     * STT_PITCH + r0] = acc[mt][nt][0];
                        st[(c0 + 1) * STT_PITCH + r0] = acc[mt][nt][1];
                        st[(c0)     * STT_PITCH + r1] = acc[mt][nt][2];
                        st[(c0 + 1) * STT_PITCH + r1] = acc[mt][nt][3];
                    }
                }
            }
            __syncthreads();
            #pragma unroll
            for (int i = 0; i < 8; ++i) {      // 64 rows x 32 float4
                int idx = i * TPB + tid;
                int mc = idx >> 5, g = idx & 31;
                float4 w = *(const float4*)(st + mc * STT_PITCH + g * 4);
                stg_cs128(ob + (size_t)(tjbase + half * 64 + mc) * BN + tibase + g * 4, w);
            }
        }
    }
}

extern "C" void kernel_launch(void* const* d_in, const int* in_sizes, int n_in,
                              void* d_out, int out_size) {
    const float* x = (const float*)d_in[0];
    float* out = (float*)d_out;

    cudaFuncSetAttribute(hx_mma<0>, cudaFuncAttributeMaxDynamicSharedMemorySize, SM_TOTAL);
    cudaFuncSetAttribute(hx_mma<1>, cudaFuncAttributeMaxDynamicSharedMemorySize, SM_TOTAL);

    hx_prep<<<(NB * BN * BD / 4) / 256, 256>>>(x);     // fp16 convert + sq + init
    hx_mma<0><<<NBLK, TPB, SM_TOTAL>>>(out);           // global min/max of d2
    hx_mma<1><<<NBLK, TPB, SM_TOTAL>>>(out);           // recompute + normalize + write
}

// round 14
// speedup vs baseline: 1.1584x; 1.0465x over previous
#include <cuda_runtime.h>
#include <cuda_fp16.h>
#include <math.h>
#include <stdint.h>

// Problem shape (fixed): x = [4, 4096, 64] fp32 -> out [4, 4096, 4096] fp32
#define BN    4096
#define BD    64
#define NB    4
#define TILE  128
#define TPD   (BN / TILE)                  // 32
#define NOFF  (TPD * (TPD - 1) / 2)        // 496 off-diag pairs
#define PAIRS (NOFF + TPD)                 // 528
#define NBLK  (NB * PAIRS)                 // 2112
#define TPB   256
#define CHUNK 3
#define NGRID0 (NBLK / CHUNK)              // 704 CTAs for pass 0

// SMEM (bytes). fp16 tiles: pitch 72 halves (144B) -> conflict-free ldmatrix.
#define TILE_PITCH_B 144
#define TILE_BYTES   (128 * TILE_PITCH_B)  // 18432
// pass-0 (minmax): [0,1024) reduce pad | A0 | A1 | B0 | B1
#define MM_A0    1024
#define MM_A1    (MM_A0 + TILE_BYTES)
#define MM_B0    (MM_A1 + TILE_BYTES)
#define MM_B1    (MM_B0 + TILE_BYTES)
#define SM_MM    (MM_B1 + TILE_BYTES)      // 74752
// pass-1 (write): R13 layout
#define SM_SQA   0
#define SM_SQB   512
#define SM_T     1024
#define SM_STT   SM_T                      // fp32 [64][pitch 136]
#define STT_PITCH 136
#define SM_WR    (1024 + 2 * TILE_BYTES)   // 37888

// ---- device globals (static scratch; no allocations) ----------------------
__device__ __half  g_xh[(size_t)NB * BN * BD];
__device__ float    g_sq[NB * BN];
__device__ unsigned g_max_bits;
__device__ unsigned g_min_bits;

// ---- helpers ---------------------------------------------------------------
__device__ __forceinline__ void mma16816(float* c, const unsigned* a, const unsigned* b) {
    asm volatile(
        "mma.sync.aligned.m16n8k16.row.col.f32.f16.f16.f32 "
        "{%0,%1,%2,%3}, {%4,%5,%6,%7}, {%8,%9}, {%0,%1,%2,%3};"
        : "+f"(c[0]), "+f"(c[1]), "+f"(c[2]), "+f"(c[3])
        : "r"(a[0]), "r"(a[1]), "r"(a[2]), "r"(a[3]), "r"(b[0]), "r"(b[1]));
}
__device__ __forceinline__ void ldm_x4(unsigned* f, uint32_t addr) {
    asm volatile("ldmatrix.sync.aligned.m8n8.x4.shared.b16 {%0,%1,%2,%3}, [%4];"
        : "=r"(f[0]), "=r"(f[1]), "=r"(f[2]), "=r"(f[3]) : "r"(addr));
}
__device__ __forceinline__ float rsqrt_a(float x) {
    float r;
    asm("rsqrt.approx.f32 %0, %1;" : "=f"(r) : "f"(x));
    return r;
}
__device__ __forceinline__ void stg_cs64(float* p, float a, float b) {
    asm volatile("st.global.cs.v2.f32 [%0], {%1,%2};" :: "l"(p), "f"(a), "f"(b) : "memory");
}
__device__ __forceinline__ void stg_cs128(float* p, float4 v) {
    asm volatile("st.global.cs.v4.f32 [%0], {%1,%2,%3,%4};"
                 :: "l"(p), "f"(v.x), "f"(v.y), "f"(v.z), "f"(v.w) : "memory");
}
__device__ __forceinline__ void cp16(uint32_t dst, const void* src) {
    asm volatile("cp.async.ca.shared.global [%0], [%1], 16;" :: "r"(dst), "l"(src) : "memory");
}

// ---- prep: x -> fp16, row sums of squares (fp32), init min/max -------------
__global__ __launch_bounds__(256) void hx_prep(const float* __restrict__ x) {
    if (blockIdx.x == 0 && threadIdx.x == 0) {
        g_max_bits = 0u;
        g_min_bits = 0x7F7FFFFFu;
    }
    int f = blockIdx.x * 256 + threadIdx.x;
    float4 v = ((const float4*)x)[f];

    __half2 p0 = __floats2half2_rn(v.x, v.y);
    __half2 p1 = __floats2half2_rn(v.z, v.w);
    ((uint2*)g_xh)[f] = make_uint2(*(unsigned*)&p0, *(unsigned*)&p1);

    float s = v.x * v.x + v.y * v.y + v.z * v.z + v.w * v.w;
    #pragma unroll
    for (int o = 8; o; o >>= 1) s += __shfl_down_sync(0xffffffffu, s, o, 16);
    if ((threadIdx.x & 15) == 0) g_sq[f >> 4] = s;
}

// ---- pass 0: 3 pipelined tile-pairs per CTA, min/max of clamped d2 ---------
__global__ __launch_bounds__(TPB, 2) void hx_minmax() {
    extern __shared__ char smem[];
    const int tid  = threadIdx.x;
    const int wid  = tid >> 5;
    const int lane = tid & 31;
    const int q    = lane >> 2;
    const int t4   = lane & 3;
    const int wm   = wid >> 2;
    const int wn   = wid & 3;

    // Decode this CTA's CHUNK consecutive pairs (ti-major incl. diagonal so
    // same-ti runs are contiguous -> A tile reused across pairs).
    int bv[CHUNK], tiv[CHUNK], tjv[CHUNK];
    #pragma unroll
    for (int s = 0; s < CHUNK; ++s) {
        int g = blockIdx.x * CHUNK + s;
        int b = g / PAIRS;
        int p = g - b * PAIRS;
        int ti = 0, span = TPD;
        while (p >= span) { p -= span; --span; ++ti; }
        bv[s] = b; tiv[s] = ti; tjv[s] = ti + p;
    }

    uint32_t smemBase = (uint32_t)__cvta_generic_to_shared(smem);
    auto issueTile = [&](uint32_t dstOff, int b, int trow) {
        #pragma unroll
        for (int i = 0; i < 4; ++i) {
            int idx = i * TPB + tid;         // 0..1023
            int row = idx >> 3;
            int ch  = idx & 7;
            cp16(smemBase + dstOff + row * TILE_PITCH_B + ch * 16,
                 g_xh + ((size_t)b * BN + trow * TILE + row) * BD + ch * 8);
        }
    };

    // Prologue: group G0 = {A(pair0), B(pair0)}.
    issueTile(MM_A0, bv[0], tiv[0]);
    issueTile(MM_B0, bv[0], tjv[0]);
    asm volatile("cp.async.commit_group;" ::: "memory");

    float tmax = 0.f, tmin = 3.402823466e38f;
    int curA = 0;

    // Lane-invariant addressing components.
    const int aRow = lane & 15;
    const int aCol = (lane >> 4) << 4;
    const int bRow = lane & 7;
    const int bCol = (lane & 8) ? 16 : 0;
    const int bSel = (lane >> 4) & 1;

    #pragma unroll
    for (int s = 0; s < CHUNK; ++s) {
        int nextA = curA;
        if (s < CHUNK - 1) {                 // prefetch pair s+1 (group G_{s+1})
            bool chg = (tiv[s + 1] != tiv[s]) || (bv[s + 1] != bv[s]);
            if (chg) {
                nextA = curA ^ 1;
                issueTile(nextA ? MM_A1 : MM_A0, bv[s + 1], tiv[s + 1]);
            }
            issueTile(((s + 1) & 1) ? MM_B1 : MM_B0, bv[s + 1], tjv[s + 1]);
            asm volatile("cp.async.commit_group;" ::: "memory");
        }

        // Prefetch sq into registers (L2-hot; latency hidden under HMMA).
        float sr0[4], sr1[4], sc0[4], sc1[4];
        {
            const float* sq = g_sq + bv[s] * BN;
            const int tib = tiv[s] * TILE, tjb = tjv[s] * TILE;
            #pragma unroll
            for (int mt = 0; mt < 4; ++mt) {
                sr0[mt] = sq[tib + wm * 64 + mt * 16 + q];
                sr1[mt] = sq[tib + wm * 64 + mt * 16 + q + 8];
            }
            #pragma unroll
            for (int nt = 0; nt < 4; ++nt) {
                sc0[nt] = sq[tjb + wn * 32 + nt * 8 + t4 * 2];
                sc1[nt] = sq[tjb + wn * 32 + nt * 8 + t4 * 2 + 1];
            }
        }

        if (s < CHUNK - 1) asm volatile("cp.async.wait_group 1;" ::: "memory");
        else               asm volatile("cp.async.wait_group 0;" ::: "memory");
        __syncthreads();

        uint32_t aB = smemBase + (curA ? MM_A1 : MM_A0);
        uint32_t bB = smemBase + ((s & 1) ? MM_B1 : MM_B0);
        uint32_t aAddr[4], bAddr[2];
        #pragma unroll
        for (int mt = 0; mt < 4; ++mt)
            aAddr[mt] = aB + (uint32_t)((wm * 64 + mt * 16 + aRow) * TILE_PITCH_B + aCol);
        #pragma unroll
        for (int j = 0; j < 2; ++j) {
            int n0 = wn * 32 + (2 * j + bSel) * 8 + bRow;
            bAddr[j] = bB + (uint32_t)(n0 * TILE_PITCH_B + bCol);
        }

        float acc[4][4][4];
        #pragma unroll
        for (int i = 0; i < 4; ++i)
            #pragma unroll
            for (int j = 0; j < 4; ++j)
                #pragma unroll
                for (int e = 0; e < 4; ++e) acc[i][j][e] = 0.f;

        #pragma unroll
        for (int kc = 0; kc < 4; ++kc) {
            unsigned A[4][4], B[4][2];
            #pragma unroll
            for (int mt = 0; mt < 4; ++mt) ldm_x4(A[mt], aAddr[mt] + kc * 32);
            {
                unsigned u0[4], u1[4];
                ldm_x4(u0, bAddr[0] + kc * 32);
                ldm_x4(u1, bAddr[1] + kc * 32);
                B[0][0] = u0[0]; B[0][1] = u0[1]; B[1][0] = u0[2]; B[1][1] = u0[3];
                B[2][0] = u1[0]; B[2][1] = u1[1]; B[3][0] = u1[2]; B[3][1] = u1[3];
            }
            #pragma unroll
            for (int mt = 0; mt < 4; ++mt)
                #pragma unroll
                for (int nt = 0; nt < 4; ++nt) mma16816(acc[mt][nt], A[mt], B[nt]);
        }

        #pragma unroll
        for (int mt = 0; mt < 4; ++mt)
            #pragma unroll
            for (int nt = 0; nt < 4; ++nt) {
                float d00 = fmaxf(fmaf(-2.f, acc[mt][nt][0], sr0[mt] + sc0[nt]), 0.f);
                float d01 = fmaxf(fmaf(-2.f, acc[mt][nt][1], sr0[mt] + sc1[nt]), 0.f);
                float d10 = fmaxf(fmaf(-2.f, acc[mt][nt][2], sr1[mt] + sc0[nt]), 0.f);
                float d11 = fmaxf(fmaf(-2.f, acc[mt][nt][3], sr1[mt] + sc1[nt]), 0.f);
                tmax = fmaxf(tmax, fmaxf(fmaxf(d00, d01), fmaxf(d10, d11)));
                tmin = fminf(tmin, fminf(fminf(d00, d01), fminf(d10, d11)));
            }

        __syncthreads();                     // all warps done with buffers
        curA = nextA;
    }

    // Single block reduce + one atomic pair per CTA.
    #pragma unroll
    for (int o = 16; o; o >>= 1) {
        tmax = fmaxf(tmax, __shfl_xor_sync(0xffffffffu, tmax, o));
        tmin = fminf(tmin, __shfl_xor_sync(0xffffffffu, tmin, o));
    }
    float* redmx = (float*)smem;
    float* redmn = redmx + 8;
    if (lane == 0) { redmx[wid] = tmax; redmn[wid] = tmin; }
    __syncthreads();
    if (wid == 0 && lane < 8) {
        float m = redmx[lane], n = redmn[lane];
        #pragma unroll
        for (int o = 4; o; o >>= 1) {
            m = fmaxf(m, __shfl_down_sync(0xffu, m, o, 8));
            n = fminf(n, __shfl_down_sync(0xffu, n, o, 8));
        }
        if (lane == 0) {
            atomicMax(&g_max_bits, __float_as_uint(m));
            atomicMin(&g_min_bits, __float_as_uint(n));
        }
    }
}

// ---- pass 1: recompute + normalize + write (unchanged from R13) ------------
__global__ __launch_bounds__(TPB, 2) void hx_write(float* __restrict__ out) {
    extern __shared__ char smem[];
    const int tid  = threadIdx.x;
    const int wid  = tid >> 5;
    const int lane = tid & 31;
    const int q    = lane >> 2;
    const int t4   = lane & 3;
    const int wm   = wid >> 2;
    const int wn   = wid & 3;

    // Off-diag pairs first, diagonal last (cheap CTAs in the partial wave).
    int bidx = blockIdx.x;
    int b = bidx / PAIRS;
    int p = bidx - b * PAIRS;
    int ti, tj;
    if (p < NOFF) {
        ti = 0;
        int span = TPD - 1;
        while (p >= span) { p -= span; --span; ++ti; }
        tj = ti + 1 + p;
    } else {
        ti = tj = p - NOFF;
    }
    const bool diag = (ti == tj);
    const int tibase = ti * TILE, tjbase = tj * TILE;

    float d2min = __uint_as_float(g_min_bits);
    float d2max = __uint_as_float(g_max_bits);
    float mn  = (d2min > 0.f) ? d2min * rsqrt_a(d2min) : 0.f;
    float inv = 1.0f / (d2max * rsqrt_a(d2max) - mn);

    uint32_t smemBase = (uint32_t)__cvta_generic_to_shared(smem);

    #pragma unroll
    for (int it = 0; it < 8; ++it) {
        int idx = it * TPB + tid;
        int t   = idx >> 10;
        int rem = idx & 1023;
        int row = rem >> 3;
        int ch  = rem & 7;
        int row0 = (t ? tj : ti) * TILE;
        cp16(smemBase + SM_T + t * TILE_BYTES + row * TILE_PITCH_B + ch * 16,
             g_xh + ((size_t)b * BN + row0 + row) * BD + ch * 8);
    }
    asm volatile("cp.async.commit_group;" ::: "memory");
    if (tid < 128)       ((float*)(smem + SM_SQA))[tid]       = g_sq[b * BN + tibase + tid];
    else                 ((float*)(smem + SM_SQB))[tid - 128] = g_sq[b * BN + tjbase + tid - 128];
    asm volatile("cp.async.wait_group 0;" ::: "memory");
    __syncthreads();

    uint32_t sBase = smemBase + SM_T;
    uint32_t aAddr[4], bAddr[2];
    {
        int aRow = lane & 15;
        int aCol = (lane >> 4) << 4;
        #pragma unroll
        for (int mt = 0; mt < 4; ++mt)
            aAddr[mt] = sBase + (uint32_t)((wm * 64 + mt * 16 + aRow) * TILE_PITCH_B + aCol);
        int bRow = lane & 7;
        int bCol = (lane & 8) ? 16 : 0;
        int bSel = (lane >> 4) & 1;
        #pragma unroll
        for (int j = 0; j < 2; ++j) {
            int n0 = wn * 32 + (2 * j + bSel) * 8 + bRow;
            bAddr[j] = sBase + (uint32_t)(TILE_BYTES + n0 * TILE_PITCH_B + bCol);
        }
    }

    float acc[4][4][4];
    #pragma unroll
    for (int i = 0; i < 4; ++i)
        #pragma unroll
        for (int j = 0; j < 4; ++j)
            #pragma unroll
            for (int e = 0; e < 4; ++e) acc[i][j][e] = 0.f;

    #pragma unroll
    for (int kc = 0; kc < 4; ++kc) {
        unsigned A[4][4], B[4][2];
        #pragma unroll
        for (int mt = 0; mt < 4; ++mt) ldm_x4(A[mt], aAddr[mt] + kc * 32);
        {
            unsigned u0[4], u1[4];
            ldm_x4(u0, bAddr[0] + kc * 32);
            ldm_x4(u1, bAddr[1] + kc * 32);
            B[0][0] = u0[0]; B[0][1] = u0[1]; B[1][0] = u0[2]; B[1][1] = u0[3];
            B[2][0] = u1[0]; B[2][1] = u1[1]; B[3][0] = u1[2]; B[3][1] = u1[3];
        }
        #pragma unroll
        for (int mt = 0; mt < 4; ++mt)
            #pragma unroll
            for (int nt = 0; nt < 4; ++nt) mma16816(acc[mt][nt], A[mt], B[nt]);
    }

    const float* sqa = (const float*)(smem + SM_SQA);
    const float* sqb = (const float*)(smem + SM_SQB);
    float sr0[4], sr1[4], sc0[4], sc1[4];
    #pragma unroll
    for (int mt = 0; mt < 4; ++mt) {
        sr0[mt] = sqa[wm * 64 + mt * 16 + q];
        sr1[mt] = sqa[wm * 64 + mt * 16 + q + 8];
    }
    #pragma unroll
    for (int nt = 0; nt < 4; ++nt) {
        sc0[nt] = sqb[wn * 32 + nt * 8 + t4 * 2];
        sc1[nt] = sqb[wn * 32 + nt * 8 + t4 * 2 + 1];
    }

    float* ob = out + (size_t)b * BN * BN;
    #pragma unroll
    for (int mt = 0; mt < 4; ++mt) {
        int r0 = wm * 64 + mt * 16 + q, r1 = r0 + 8;
        #pragma unroll
        for (int nt = 0; nt < 4; ++nt) {
            int c0 = wn * 32 + nt * 8 + t4 * 2;
            float d2, d;
            d2 = fmaf(-2.f, acc[mt][nt][0], sr0[mt] + sc0[nt]);
            d  = (d2 > 0.f) ? d2 * rsqrt_a(d2) : 0.f;
            acc[mt][nt][0] = (diag && r0 == c0)     ? 1.0f : (d - mn) * inv;
            d2 = fmaf(-2.f, acc[mt][nt][1], sr0[mt] + sc1[nt]);
            d  = (d2 > 0.f) ? d2 * rsqrt_a(d2) : 0.f;
            acc[mt][nt][1] = (diag && r0 == c0 + 1) ? 1.0f : (d - mn) * inv;
            d2 = fmaf(-2.f, acc[mt][nt][2], sr1[mt] + sc0[nt]);
            d  = (d2 > 0.f) ? d2 * rsqrt_a(d2) : 0.f;
            acc[mt][nt][2] = (diag && r1 == c0)     ? 1.0f : (d - mn) * inv;
            d2 = fmaf(-2.f, acc[mt][nt][3], sr1[mt] + sc1[nt]);
            d  = (d2 > 0.f) ? d2 * rsqrt_a(d2) : 0.f;
            acc[mt][nt][3] = (diag && r1 == c0 + 1) ? 1.0f : (d - mn) * inv;
            stg_cs64(ob + (size_t)(tibase + r0) * BN + tjbase + c0,
                     acc[mt][nt][0], acc[mt][nt][1]);
            stg_cs64(ob + (size_t)(tibase + r1) * BN + tjbase + c0,
                     acc[mt][nt][2], acc[mt][nt][3]);
        }
    }

    if (!diag) {
        float* st = (float*)(smem + SM_STT);
        #pragma unroll
        for (int half = 0; half < 2; ++half) {
            __syncthreads();
            if ((wn >> 1) == half) {
                #pragma unroll
                for (int mt = 0; mt < 4; ++mt) {
                    int r0 = wm * 64 + mt * 16 + q, r1 = r0 + 8;
                    #pragma unroll
                    for (int nt = 0; nt < 4; ++nt) {
                        int c0 = wn * 32 + nt * 8 + t4 * 2 - half * 64;
                        st[(c0)     * STT_PITCH + r0] = acc[mt][nt][0];
                        st[(c0 + 1) * STT_PITCH + r0] = acc[mt][nt][1];
                        st[(c0)     * STT_PITCH + r1] = acc[mt][nt][2];
                        st[(c0 + 1) * STT_PITCH + r1] = acc[mt][nt][3];
                    }
                }
            }
            __syncthreads();
            #pragma unroll
            for (int i = 0; i < 8; ++i) {
                int idx = i * TPB + tid;
                int mc = idx >> 5, g = idx & 31;
                float4 w = *(const float4*)(st + mc * STT_PITCH + g * 4);
                stg_cs128(ob + (size_t)(tjbase + half * 64 + mc) * BN + tibase + g * 4, w);
            }
        }
    }
}

extern "C" void kernel_launch(void* const* d_in, const int* in_sizes, int n_in,
                              void* d_out, int out_size) {
    const float* x = (const float*)d_in[0];
    float* out = (float*)d_out;

    cudaFuncSetAttribute(hx_minmax, cudaFuncAttributeMaxDynamicSharedMemorySize, SM_MM);
    cudaFuncSetAttribute(hx_write,  cudaFuncAttributeMaxDynamicSharedMemorySize, SM_WR);

    hx_prep<<<(NB * BN * BD / 4) / 256, 256>>>(x);     // fp16 convert + sq + init
    hx_minmax<<<NGRID0, TPB, SM_MM>>>();               // pipelined min/max of d2
    hx_write<<<NBLK, TPB, SM_WR>>>(out);               // recompute + normalize + write
}